// round 9
// baseline (speedup 1.0000x reference)
#include <cuda_runtime.h>
#include <cuda_fp16.h>
#include <cstdint>
#include <stdint.h>

// Problem constants (fixed by the dataset)
#define BB   512
#define TT   256
#define HH   256
#define HORZ 22
#define TILE_B 4
#define NCTA (BB / TILE_B)     // 128 CTAs, ~1 per SM
#define NTHREADS 256           // 128 column-pairs x 2 batch-groups
#define HP   (HH / 2)          // 128 pairs

// Packed fp16 copies of the recurrent matrices.
// g_Uzr[i2*HP+jp] = { Uz[2i2][2jp..2jp+1], Uz[2i2+1][...], Ur[2i2][...], Ur[2i2+1][...] }
//   -> one LDG.128 per row-pair covers both z and r weights. Loaded with __ldcg
//      (L2-only) so it never evicts Uh from L1.
// g_Uhp[i2*HP+jp] = { Uh[2i2][2jp..2jp+1], Uh[2i2+1][2jp..2jp+1] }
//   -> default .ca loads; 128 KB working set becomes L1-resident after step 0.
__device__ uint4 g_Uzr[HP * HP];
__device__ uint2 g_Uhp[HP * HP];

__device__ __forceinline__ uint32_t pack_h2(float a, float b) {
    __half2 h = __floats2half2_rn(a, b);
    return *reinterpret_cast<uint32_t*>(&h);
}

__global__ void convert_kernel(const float* __restrict__ Uz,
                               const float* __restrict__ Ur,
                               const float* __restrict__ Uh) {
    int idx = blockIdx.x * blockDim.x + threadIdx.x;   // over HP*HP entries
    if (idx < HP * HP) {
        const int i2 = idx / HP;
        const int jp = idx % HP;
        const int r0 = 2 * i2, c0 = 2 * jp;
        uint4 v;
        v.x = pack_h2(Uz[r0 * HH + c0],       Uz[r0 * HH + c0 + 1]);
        v.y = pack_h2(Uz[(r0 + 1) * HH + c0], Uz[(r0 + 1) * HH + c0 + 1]);
        v.z = pack_h2(Ur[r0 * HH + c0],       Ur[r0 * HH + c0 + 1]);
        v.w = pack_h2(Ur[(r0 + 1) * HH + c0], Ur[(r0 + 1) * HH + c0 + 1]);
        g_Uzr[idx] = v;
        uint2 w;
        w.x = pack_h2(Uh[r0 * HH + c0],       Uh[r0 * HH + c0 + 1]);
        w.y = pack_h2(Uh[(r0 + 1) * HH + c0], Uh[(r0 + 1) * HH + c0 + 1]);
        g_Uhp[idx] = w;
    }
}

__device__ __forceinline__ float sigmf(float v) { return 1.0f / (1.0f + expf(-v)); }

__device__ __forceinline__ __half2 u2h(uint32_t u) {
    return *reinterpret_cast<__half2*>(&u);
}

__device__ __forceinline__ float2 pair_sum(__half2 a, __half2 b) {
    float2 fa = __half22float2(a);
    float2 fb = __half22float2(b);
    return make_float2(fa.x + fb.x, fa.y + fb.y);
}

__global__ __launch_bounds__(NTHREADS, 1)
void garch_gru_kernel(
    const float* __restrict__ x,        // (B, T, 1)
    const float* __restrict__ Wz_w,     // (1, H)
    const float* __restrict__ Wz_b,     // (H,)
    const float* __restrict__ Uz_b,     // (H,)
    const float* __restrict__ Wr_w,
    const float* __restrict__ Wr_b,
    const float* __restrict__ Ur_b,
    const float* __restrict__ Wh_w,
    const float* __restrict__ Wh_b,
    const float* __restrict__ Uh_b,
    const float* __restrict__ Wg_w,     // (1, H)
    const float* __restrict__ Wg_b,     // (H,)
    const float* __restrict__ omega_raw,
    const float* __restrict__ alpha_raw,
    const float* __restrict__ beta_raw,
    const float* __restrict__ gamma_p,
    const float* __restrict__ fc1_w,    // (H, H)
    const float* __restrict__ fc1_b,    // (H,)
    const float* __restrict__ fc2_w,    // (H, HORZ)
    const float* __restrict__ fc2_b,    // (HORZ,)
    float* __restrict__ out)            // vol (B, HORZ) then sigma_sq (B,)
{
    // h replicated per-batch, packed as row pairs:
    // hdup[buf][i2][lb] = { dup(h[2*i2]), dup(h[2*i2+1]) } each as half2 {v,v}
    __shared__ uint2 hdup[2][HP][TILE_B];     // 8 KB
    __shared__ uint2 rhdup[HP][TILE_B];       // 4 KB
    __shared__ float hid_s[TILE_B][HH];       // 4 KB (epilogue)
    __shared__ float sig_s[TILE_B];

    const int tid = threadIdx.x;
    const int jp  = tid & 127;        // column-pair index: columns j0=2jp, j1=2jp+1
    const int bg  = tid >> 7;         // batch group: handles local batches 2bg, 2bg+1
    const int j0  = jp * 2;
    const int lA  = bg * 2;
    const int lB  = lA + 1;
    const int b0  = blockIdx.x * TILE_B;
    const int gA  = b0 + lA;
    const int gB  = b0 + lB;

    // Per-column constants (fp32)
    const float2 wz = *reinterpret_cast<const float2*>(&Wz_w[j0]);
    const float2 wr = *reinterpret_cast<const float2*>(&Wr_w[j0]);
    const float2 wh = *reinterpret_cast<const float2*>(&Wh_w[j0]);
    const float2 wg = *reinterpret_cast<const float2*>(&Wg_w[j0]);
    const float2 bgc = *reinterpret_cast<const float2*>(&Wg_b[j0]);
    float2 cz, cr, ch;
    {
        float2 a1 = *reinterpret_cast<const float2*>(&Wz_b[j0]);
        float2 a2 = *reinterpret_cast<const float2*>(&Uz_b[j0]);
        cz = make_float2(a1.x + a2.x, a1.y + a2.y);
        a1 = *reinterpret_cast<const float2*>(&Wr_b[j0]);
        a2 = *reinterpret_cast<const float2*>(&Ur_b[j0]);
        cr = make_float2(a1.x + a2.x, a1.y + a2.y);
        a1 = *reinterpret_cast<const float2*>(&Wh_b[j0]);
        a2 = *reinterpret_cast<const float2*>(&Uh_b[j0]);
        ch = make_float2(a1.x + a2.x, a1.y + a2.y);
    }

    // Scalar params
    const float om_r  = *omega_raw;
    const float omega = log1pf(expf(om_r)) + 1e-6f;   // softplus + 1e-6
    const float A_    = sigmf(*alpha_raw);
    const float Bb    = sigmf(*beta_raw) * (1.0f - A_ * 0.99f);
    const float gam   = *gamma_p;

    // Init h = 0
    {
        for (int b = 0; b < TILE_B; b++) {
            if (bg == 0) hdup[0][jp][b] = make_uint2(0u, 0u);
        }
    }

    // GARCH state (replicated across the 128 threads of this batch group)
    float epsqA = 1e-6f, sigsqA = 1e-6f;
    float epsqB = 1e-6f, sigsqB = 1e-6f;

    __syncthreads();

    const __half2 hzero = __half2half2(__float2half_rn(0.0f));

    for (int t = 0; t < TT; ++t) {
        const int p = t & 1;

        const float xA = x[gA * TT + t];
        const float xB = x[gB * TT + t];

        const float ginA = omega + A_ * epsqA + Bb * sigsqA;
        const float ginB = omega + A_ * epsqB + Bb * sigsqB;
        sigsqA = ginA; epsqA = xA * xA;
        sigsqB = ginB; epsqB = xB * xB;

        // ---- z / r mat-vecs (fp16, dual parity accumulators) ----
        __half2 azA0 = hzero, azA1 = hzero, arA0 = hzero, arA1 = hzero;
        __half2 azB0 = hzero, azB1 = hzero, arB0 = hzero, arB1 = hzero;

        const uint2* hrow = &hdup[p][0][0];
        #pragma unroll 8
        for (int i2 = 0; i2 < HP; i2++) {
            const uint2 hA = hrow[i2 * TILE_B + lA];          // broadcast LDS.64
            const uint2 hB = hrow[i2 * TILE_B + lB];
            const uint4 uzr = __ldcg(&g_Uzr[i2 * HP + jp]);   // LDG.128, L2-only
            azA0 = __hfma2(u2h(uzr.x), u2h(hA.x), azA0);
            azA1 = __hfma2(u2h(uzr.y), u2h(hA.y), azA1);
            arA0 = __hfma2(u2h(uzr.z), u2h(hA.x), arA0);
            arA1 = __hfma2(u2h(uzr.w), u2h(hA.y), arA1);
            azB0 = __hfma2(u2h(uzr.x), u2h(hB.x), azB0);
            azB1 = __hfma2(u2h(uzr.y), u2h(hB.y), azB1);
            arB0 = __hfma2(u2h(uzr.z), u2h(hB.x), arB0);
            arB1 = __hfma2(u2h(uzr.w), u2h(hB.y), arB1);
        }

        const float2 szA = pair_sum(azA0, azA1);
        const float2 srA = pair_sum(arA0, arA1);
        const float2 szB = pair_sum(azB0, azB1);
        const float2 srB = pair_sum(arB0, arB1);

        const float zA0 = sigmf(xA * wz.x + cz.x + szA.x);
        const float zA1 = sigmf(xA * wz.y + cz.y + szA.y);
        const float rA0 = sigmf(xA * wr.x + cr.x + srA.x);
        const float rA1 = sigmf(xA * wr.y + cr.y + srA.y);
        const float zB0 = sigmf(xB * wz.x + cz.x + szB.x);
        const float zB1 = sigmf(xB * wz.y + cz.y + szB.y);
        const float rB0 = sigmf(xB * wr.x + cr.x + srB.x);
        const float rB1 = sigmf(xB * wr.y + cr.y + srB.y);

        // previous h for our own (batch, column-pair) slots
        const uint2 hopA = hdup[p][jp][lA];
        const uint2 hopB = hdup[p][jp][lB];
        const float hoA0 = __low2float(u2h(hopA.x));
        const float hoA1 = __low2float(u2h(hopA.y));
        const float hoB0 = __low2float(u2h(hopB.x));
        const float hoB1 = __low2float(u2h(hopB.y));

        {
            uint2 v;
            const uint32_t a0 = pack_h2(rA0 * hoA0, rA0 * hoA0);
            const uint32_t a1 = pack_h2(rA1 * hoA1, rA1 * hoA1);
            v.x = a0; v.y = a1;
            rhdup[jp][lA] = v;
            const uint32_t b0_ = pack_h2(rB0 * hoB0, rB0 * hoB0);
            const uint32_t b1_ = pack_h2(rB1 * hoB1, rB1 * hoB1);
            v.x = b0_; v.y = b1_;
            rhdup[jp][lB] = v;
        }
        __syncthreads();

        // ---- h_tilde mat-vec over (r*h); Uh loads are .ca -> L1-resident ----
        __half2 ahA0 = hzero, ahA1 = hzero, ahB0 = hzero, ahB1 = hzero;
        const uint2* rrow = &rhdup[0][0];
        #pragma unroll 8
        for (int i2 = 0; i2 < HP; i2++) {
            const uint2 rA = rrow[i2 * TILE_B + lA];
            const uint2 rB = rrow[i2 * TILE_B + lB];
            const uint2 uh = g_Uhp[i2 * HP + jp];
            ahA0 = __hfma2(u2h(uh.x), u2h(rA.x), ahA0);
            ahA1 = __hfma2(u2h(uh.y), u2h(rA.y), ahA1);
            ahB0 = __hfma2(u2h(uh.x), u2h(rB.x), ahB0);
            ahB1 = __hfma2(u2h(uh.y), u2h(rB.y), ahB1);
        }
        const float2 shA = pair_sum(ahA0, ahA1);
        const float2 shB = pair_sum(ahB0, ahB1);

        const float htA0 = tanhf(xA * wh.x + ch.x + shA.x);
        const float htA1 = tanhf(xA * wh.y + ch.y + shA.y);
        const float htB0 = tanhf(xB * wh.x + ch.x + shB.x);
        const float htB1 = tanhf(xB * wh.y + ch.y + shB.y);

        const float gtA0 = ginA * wg.x + bgc.x;
        const float gtA1 = ginA * wg.y + bgc.y;
        const float gtB0 = ginB * wg.x + bgc.x;
        const float gtB1 = ginB * wg.y + bgc.y;

        const float hnA0 = tanhf((1.0f - zA0) * htA0 + zA0 * hoA0 + gam * gtA0);
        const float hnA1 = tanhf((1.0f - zA1) * htA1 + zA1 * hoA1 + gam * gtA1);
        const float hnB0 = tanhf((1.0f - zB0) * htB0 + zB0 * hoB0 + gam * gtB0);
        const float hnB1 = tanhf((1.0f - zB1) * htB1 + zB1 * hoB1 + gam * gtB1);

        const int q = 1 - p;
        {
            uint2 v;
            v.x = pack_h2(hnA0, hnA0);
            v.y = pack_h2(hnA1, hnA1);
            hdup[q][jp][lA] = v;
            v.x = pack_h2(hnB0, hnB0);
            v.y = pack_h2(hnB1, hnB1);
            hdup[q][jp][lB] = v;
        }
        __syncthreads();
    }

    // TT is even -> final h lives in buffer 0.

    // ---- epilogue: hid = relu(h @ fc1 + fc1_b), fp32 ----
    {
        float aA0 = 0.f, aA1 = 0.f, aB0 = 0.f, aB1 = 0.f;
        for (int i2 = 0; i2 < HP; i2++) {
            const uint2 hA = hdup[0][i2][lA];
            const uint2 hB = hdup[0][i2][lB];
            const float hA0 = __low2float(u2h(hA.x));
            const float hA1 = __low2float(u2h(hA.y));
            const float hB0 = __low2float(u2h(hB.x));
            const float hB1 = __low2float(u2h(hB.y));
            const float2 w0 = *reinterpret_cast<const float2*>(&fc1_w[(2 * i2) * HH + j0]);
            const float2 w1 = *reinterpret_cast<const float2*>(&fc1_w[(2 * i2 + 1) * HH + j0]);
            aA0 += hA0 * w0.x + hA1 * w1.x;
            aA1 += hA0 * w0.y + hA1 * w1.y;
            aB0 += hB0 * w0.x + hB1 * w1.x;
            aB1 += hB0 * w0.y + hB1 * w1.y;
        }
        const float2 b1 = *reinterpret_cast<const float2*>(&fc1_b[j0]);
        hid_s[lA][j0]     = fmaxf(aA0 + b1.x, 0.0f);
        hid_s[lA][j0 + 1] = fmaxf(aA1 + b1.y, 0.0f);
        hid_s[lB][j0]     = fmaxf(aB0 + b1.x, 0.0f);
        hid_s[lB][j0 + 1] = fmaxf(aB1 + b1.y, 0.0f);
    }
    if (tid == 0)   { sig_s[0] = sigsqA; sig_s[1] = sigsqB; }
    if (tid == 128) { sig_s[2] = sigsqA; sig_s[3] = sigsqB; }
    __syncthreads();

    // ---- fc2 + softplus + vol ----
    if (tid < TILE_B * HORZ) {
        const int lb = tid / HORZ;
        const int k  = tid % HORZ;
        float acc = fc2_b[k];
        for (int jj = 0; jj < HH; jj++)
            acc += hid_s[lb][jj] * fc2_w[jj * HORZ + k];
        const float nn = (acc > 20.0f) ? acc : log1pf(expf(acc));
        const float vb = sqrtf(sig_s[lb] + 1e-8f);
        float vol = vb * (1.0f + nn);
        vol = fminf(fmaxf(vol, 0.01f), 10.0f);
        out[(b0 + lb) * HORZ + k] = vol;
    }
    if (tid < TILE_B) {
        out[BB * HORZ + b0 + tid] = sig_s[tid];
    }
}

extern "C" void kernel_launch(void* const* d_in, const int* in_sizes, int n_in,
                              void* d_out, int out_size) {
    const float* x         = (const float*)d_in[0];
    const float* Wz_w      = (const float*)d_in[1];
    const float* Wz_b      = (const float*)d_in[2];
    const float* Uz_w      = (const float*)d_in[3];
    const float* Uz_b      = (const float*)d_in[4];
    const float* Wr_w      = (const float*)d_in[5];
    const float* Wr_b      = (const float*)d_in[6];
    const float* Ur_w      = (const float*)d_in[7];
    const float* Ur_b      = (const float*)d_in[8];
    const float* Wh_w      = (const float*)d_in[9];
    const float* Wh_b      = (const float*)d_in[10];
    const float* Uh_w      = (const float*)d_in[11];
    const float* Uh_b      = (const float*)d_in[12];
    const float* Wg_w      = (const float*)d_in[13];
    const float* Wg_b      = (const float*)d_in[14];
    const float* omega_raw = (const float*)d_in[15];
    const float* alpha_raw = (const float*)d_in[16];
    const float* beta_raw  = (const float*)d_in[17];
    const float* gamma_p   = (const float*)d_in[18];
    const float* fc1_w     = (const float*)d_in[19];
    const float* fc1_b     = (const float*)d_in[20];
    const float* fc2_w     = (const float*)d_in[21];
    const float* fc2_b     = (const float*)d_in[22];
    float* out = (float*)d_out;

    convert_kernel<<<(HP * HP + 255) / 256, 256>>>(Uz_w, Ur_w, Uh_w);
    garch_gru_kernel<<<NCTA, NTHREADS>>>(
        x, Wz_w, Wz_b, Uz_b, Wr_w, Wr_b, Ur_b, Wh_w, Wh_b, Uh_b,
        Wg_w, Wg_b, omega_raw, alpha_raw, beta_raw, gamma_p,
        fc1_w, fc1_b, fc2_w, fc2_b, out);
}